// round 1
// baseline (speedup 1.0000x reference)
#include <cuda_runtime.h>
#include <math.h>

// ---------------------------------------------------------------------------
// SimpleAttention: X[4,2048,1024] -> Q,K,V proj -> softmax(QK^T/sqrt(h))V -> out proj
// Round 0: fp32 SIMT tiled SGEMM baseline (correctness + profile anchor).
// ---------------------------------------------------------------------------

#define BM 128
#define BN 128
#define BK 8
#define TM 8
#define TN 8
// threads per block = (BM/TM)*(BN/TN) = 16*16 = 256

static const int B_SZ   = 4;
static const int SEQ    = 2048;
static const int HID    = 1024;
static const int MTOT   = B_SZ * SEQ;   // 8192

// Scratch (static __device__ arrays: allocation-free per harness rules)
__device__ float gQ[8192 * 1024];
__device__ float gK[8192 * 1024];
__device__ float gV[8192 * 1024];
__device__ float gS[(size_t)4 * 2048 * 2048];   // 64 MB scores/attn
__device__ float gC[8192 * 1024];               // context

// ---------------------------------------------------------------------------
// Tiled SGEMM.
//   TRANSB == false : C[M,N] = scale * (A[M,K] @ B[K,N]) + bias[N]?
//   TRANSB == true  : C[M,N] = scale * (A[M,K] @ B[N,K]^T)           (bias ignored)
// Batched via blockIdx.z with element strides. Assumes M%BM==0, N%BN==0, K%BK==0,
// and all row strides 16B-aligned (true for all shapes here).
// ---------------------------------------------------------------------------
template <bool TRANSB>
__global__ __launch_bounds__(256, 2)
void sgemm_kernel(const float* __restrict__ A,
                  const float* __restrict__ B,
                  const float* __restrict__ bias,
                  float* __restrict__ C,
                  int M, int N, int K, float scale,
                  size_t strideA, size_t strideB, size_t strideC)
{
    __shared__ float As[BK][BM];
    __shared__ float Bs[BK][BN];

    A += (size_t)blockIdx.z * strideA;
    B += (size_t)blockIdx.z * strideB;
    C += (size_t)blockIdx.z * strideC;

    const int bm = blockIdx.y * BM;
    const int bn = blockIdx.x * BN;
    const int tid = threadIdx.x;

    // A-tile load mapping: 128 rows x 8 k -> 256 float4 (2 per row)
    const int aRow = tid >> 1;           // 0..127
    const int aK4  = (tid & 1) * 4;      // 0 or 4
    // B-tile NN load mapping: 8 k-rows x 128 cols -> 256 float4
    const int bRow = tid >> 5;           // 0..7
    const int bCol = (tid & 31) * 4;     // 0..124

    const int ty = tid >> 4;             // 0..15
    const int tx = tid & 15;             // 0..15
    const int rowBase = ty * TM;
    const int colBase = tx * TN;

    float acc[TM][TN];
#pragma unroll
    for (int i = 0; i < TM; i++)
#pragma unroll
        for (int j = 0; j < TN; j++) acc[i][j] = 0.0f;

    for (int k0 = 0; k0 < K; k0 += BK) {
        // load A tile (transposed into As[k][m])
        float4 av = *reinterpret_cast<const float4*>(
            &A[(size_t)(bm + aRow) * K + k0 + aK4]);
        As[aK4 + 0][aRow] = av.x;
        As[aK4 + 1][aRow] = av.y;
        As[aK4 + 2][aRow] = av.z;
        As[aK4 + 3][aRow] = av.w;

        if (TRANSB) {
            // B is [N,K] row-major; want Bs[k][n] = B[bn+n][k0+k]
            float4 bv = *reinterpret_cast<const float4*>(
                &B[(size_t)(bn + aRow) * K + k0 + aK4]);
            Bs[aK4 + 0][aRow] = bv.x;
            Bs[aK4 + 1][aRow] = bv.y;
            Bs[aK4 + 2][aRow] = bv.z;
            Bs[aK4 + 3][aRow] = bv.w;
        } else {
            // B is [K,N] row-major
            float4 bv = *reinterpret_cast<const float4*>(
                &B[(size_t)(k0 + bRow) * N + bn + bCol]);
            *reinterpret_cast<float4*>(&Bs[bRow][bCol]) = bv;
        }
        __syncthreads();

#pragma unroll
        for (int k = 0; k < BK; ++k) {
            float ar[TM], br[TN];
            // vectorized smem reads (rowBase/colBase are multiples of 8 -> 16B aligned)
            *reinterpret_cast<float4*>(&ar[0]) =
                *reinterpret_cast<const float4*>(&As[k][rowBase]);
            *reinterpret_cast<float4*>(&ar[4]) =
                *reinterpret_cast<const float4*>(&As[k][rowBase + 4]);
            *reinterpret_cast<float4*>(&br[0]) =
                *reinterpret_cast<const float4*>(&Bs[k][colBase]);
            *reinterpret_cast<float4*>(&br[4]) =
                *reinterpret_cast<const float4*>(&Bs[k][colBase + 4]);
#pragma unroll
            for (int i = 0; i < TM; i++)
#pragma unroll
                for (int j = 0; j < TN; j++)
                    acc[i][j] = fmaf(ar[i], br[j], acc[i][j]);
        }
        __syncthreads();
    }

    // epilogue
#pragma unroll
    for (int i = 0; i < TM; i++) {
        const size_t row = (size_t)(bm + rowBase + i);
#pragma unroll
        for (int j = 0; j < TN; j += 4) {
            const int col = bn + colBase + j;
            float4 v;
            v.x = acc[i][j + 0] * scale;
            v.y = acc[i][j + 1] * scale;
            v.z = acc[i][j + 2] * scale;
            v.w = acc[i][j + 3] * scale;
            if (!TRANSB && bias != nullptr) {
                v.x += bias[col + 0];
                v.y += bias[col + 1];
                v.z += bias[col + 2];
                v.w += bias[col + 3];
            }
            *reinterpret_cast<float4*>(&C[row * N + col]) = v;
        }
    }
}

// ---------------------------------------------------------------------------
// Row softmax, in place. One block (256 threads) per row of length n.
// ---------------------------------------------------------------------------
__global__ __launch_bounds__(256)
void softmax_kernel(float* __restrict__ S, int n)
{
    float* row = S + (size_t)blockIdx.x * n;
    const int tid = threadIdx.x;
    __shared__ float sred[8];
    __shared__ float sbcast;

    // --- max ---
    float m = -3.402823466e38f;
    for (int i = tid; i < n; i += 256) m = fmaxf(m, row[i]);
#pragma unroll
    for (int o = 16; o > 0; o >>= 1)
        m = fmaxf(m, __shfl_xor_sync(0xffffffffu, m, o));
    if ((tid & 31) == 0) sred[tid >> 5] = m;
    __syncthreads();
    if (tid == 0) {
        float v = sred[0];
#pragma unroll
        for (int w = 1; w < 8; w++) v = fmaxf(v, sred[w]);
        sbcast = v;
    }
    __syncthreads();
    m = sbcast;

    // --- exp + sum ---
    float sum = 0.0f;
    for (int i = tid; i < n; i += 256) {
        float e = __expf(row[i] - m);
        row[i] = e;
        sum += e;
    }
#pragma unroll
    for (int o = 16; o > 0; o >>= 1)
        sum += __shfl_xor_sync(0xffffffffu, sum, o);
    __syncthreads();            // protect sred reuse
    if ((tid & 31) == 0) sred[tid >> 5] = sum;
    __syncthreads();
    if (tid == 0) {
        float v = 0.0f;
#pragma unroll
        for (int w = 0; w < 8; w++) v += sred[w];
        sbcast = 1.0f / v;
    }
    __syncthreads();
    const float inv = sbcast;
    for (int i = tid; i < n; i += 256) row[i] *= inv;
}

// ---------------------------------------------------------------------------
// Launch
// ---------------------------------------------------------------------------
extern "C" void kernel_launch(void* const* d_in, const int* in_sizes, int n_in,
                              void* d_out, int out_size)
{
    (void)in_sizes; (void)n_in; (void)out_size;
    const float* X  = (const float*)d_in[0];
    const float* Wq = (const float*)d_in[1];
    const float* bq = (const float*)d_in[2];
    const float* Wk = (const float*)d_in[3];
    const float* bk = (const float*)d_in[4];
    const float* Wv = (const float*)d_in[5];
    const float* bv = (const float*)d_in[6];
    const float* Wh = (const float*)d_in[7];
    const float* bh = (const float*)d_in[8];
    float* out = (float*)d_out;

    float *Q, *Kp, *V, *S, *C;
    cudaGetSymbolAddress((void**)&Q,  gQ);
    cudaGetSymbolAddress((void**)&Kp, gK);
    cudaGetSymbolAddress((void**)&V,  gV);
    cudaGetSymbolAddress((void**)&S,  gS);
    cudaGetSymbolAddress((void**)&C,  gC);

    const dim3 blk(256);
    const float scale = 0.03125f;  // 1/sqrt(1024)

    // QKV projections: [8192,1024] @ [1024,1024] + bias
    const dim3 gProj(HID / BN, MTOT / BM, 1);
    sgemm_kernel<false><<<gProj, blk>>>(X, Wq, bq, Q,  MTOT, HID, HID, 1.0f, 0, 0, 0);
    sgemm_kernel<false><<<gProj, blk>>>(X, Wk, bk, Kp, MTOT, HID, HID, 1.0f, 0, 0, 0);
    sgemm_kernel<false><<<gProj, blk>>>(X, Wv, bv, V,  MTOT, HID, HID, 1.0f, 0, 0, 0);

    // scores[b] = scale * Q[b] @ K[b]^T   (batched, [2048,2048])
    const dim3 gScore(SEQ / BN, SEQ / BM, B_SZ);
    sgemm_kernel<true><<<gScore, blk>>>(Q, Kp, nullptr, S,
                                        SEQ, SEQ, HID, scale,
                                        (size_t)SEQ * HID, (size_t)SEQ * HID,
                                        (size_t)SEQ * SEQ);

    // softmax over last dim
    softmax_kernel<<<B_SZ * SEQ, blk>>>(S, SEQ);

    // context[b] = attn[b] @ V[b]   ([2048,2048] @ [2048,1024])
    const dim3 gCtx(HID / BN, SEQ / BM, B_SZ);
    sgemm_kernel<false><<<gCtx, blk>>>(S, V, nullptr, C,
                                       SEQ, HID, SEQ, 1.0f,
                                       (size_t)SEQ * SEQ, (size_t)SEQ * HID,
                                       (size_t)SEQ * HID);

    // output projection: [8192,1024] @ [1024,1024] + bias
    sgemm_kernel<false><<<gProj, blk>>>(C, Wh, bh, out, MTOT, HID, HID, 1.0f, 0, 0, 0);
}

// round 12
// speedup vs baseline: 2.2449x; 2.2449x over previous
#include <cuda_runtime.h>
#include <cuda_bf16.h>
#include <cstdint>
#include <math.h>

// ---------------------------------------------------------------------------
// SimpleAttention via mma.sync bf16 (3-term split for fp32-grade accuracy).
// tcgen05 unavailable: harness PTX targets plain sm_103 (no 'a' features).
// R5 fix: ldmatrix addresses now XOR-swizzle the full logical column offset
// (prior round added k-offsets AFTER the swizzle -> carry into row bits -> NaN).
// ---------------------------------------------------------------------------

#define SEQ  2048
#define HID  1024
#define BSZ  4
#define MTOT (SEQ * BSZ)   // 8192

__device__ float gQ [(size_t)MTOT * HID];
__device__ float gK [(size_t)MTOT * HID];
__device__ float gV [(size_t)MTOT * HID];
__device__ float gVt[(size_t)MTOT * HID];
__device__ float gS [(size_t)BSZ * SEQ * SEQ];
__device__ float gC [(size_t)MTOT * HID];
__device__ float gWT[(size_t)4 * HID * HID];

// smem layout: one 64KB buffer: Ah | Al | Bh | Bl, each 128 rows x 64 bf16 (128B rows)
#define OFF_AH 0
#define OFF_AL 16384
#define OFF_BH 32768
#define OFF_BL 49152
#define GEMM_DSM (65536 + 1024)

__device__ __forceinline__ uint32_t smem_u32(const void* p) {
    uint32_t a;
    asm("{ .reg .u64 t; cvta.to.shared.u64 t, %1; cvt.u32.u64 %0, t; }"
        : "=r"(a) : "l"(p));
    return a;
}

__device__ __forceinline__ void ldsm4(uint32_t addr, uint32_t* r) {
    asm volatile("ldmatrix.sync.aligned.m8n8.x4.shared.b16 {%0,%1,%2,%3}, [%4];"
                 : "=r"(r[0]), "=r"(r[1]), "=r"(r[2]), "=r"(r[3]) : "r"(addr));
}

__device__ __forceinline__ void mma_bf16(float* d, const uint32_t* a,
                                         uint32_t b0, uint32_t b1) {
    asm volatile("mma.sync.aligned.m16n8k16.row.col.f32.bf16.bf16.f32 "
                 "{%0,%1,%2,%3}, {%4,%5,%6,%7}, {%8,%9}, {%0,%1,%2,%3};"
                 : "+f"(d[0]), "+f"(d[1]), "+f"(d[2]), "+f"(d[3])
                 : "r"(a[0]), "r"(a[1]), "r"(a[2]), "r"(a[3]), "r"(b0), "r"(b1));
}

__device__ __forceinline__ void split_store(float4 v, uint32_t hi_addr, uint32_t lo_addr) {
    __nv_bfloat16 h0 = __float2bfloat16_rn(v.x);
    __nv_bfloat16 h1 = __float2bfloat16_rn(v.y);
    __nv_bfloat16 h2 = __float2bfloat16_rn(v.z);
    __nv_bfloat16 h3 = __float2bfloat16_rn(v.w);
    float l0 = v.x - __bfloat162float(h0);
    float l1 = v.y - __bfloat162float(h1);
    float l2 = v.z - __bfloat162float(h2);
    float l3 = v.w - __bfloat162float(h3);
    __nv_bfloat162 hp0 = __nv_bfloat162(h0, h1);
    __nv_bfloat162 hp1 = __nv_bfloat162(h2, h3);
    __nv_bfloat162 lp0 = __floats2bfloat162_rn(l0, l1);
    __nv_bfloat162 lp1 = __floats2bfloat162_rn(l2, l3);
    uint32_t h01 = *reinterpret_cast<uint32_t*>(&hp0);
    uint32_t h23 = *reinterpret_cast<uint32_t*>(&hp1);
    uint32_t l01 = *reinterpret_cast<uint32_t*>(&lp0);
    uint32_t l23 = *reinterpret_cast<uint32_t*>(&lp1);
    asm volatile("st.shared.v2.b32 [%0], {%1,%2};" :: "r"(hi_addr), "r"(h01), "r"(h23) : "memory");
    asm volatile("st.shared.v2.b32 [%0], {%1,%2};" :: "r"(lo_addr), "r"(l01), "r"(l23) : "memory");
}

// ---------------------------------------------------------------------------
// GEMM: C[M,N] = scale * (A[M,K] @ B[N,K]^T) (+ bias[N])
// A, B row-major K-major. Batched via blockIdx.z element strides.
// M%128==0, N%128==0, K%64==0.
// ---------------------------------------------------------------------------
__global__ __launch_bounds__(256, 1)
void gemm_mma(const float* __restrict__ A, const float* __restrict__ B,
              const float* __restrict__ bias, float* __restrict__ C,
              int M, int N, int K, float scale,
              size_t sA, size_t sB, size_t sC)
{
    extern __shared__ char dsm[];
    A += (size_t)blockIdx.z * sA;
    B += (size_t)blockIdx.z * sB;
    C += (size_t)blockIdx.z * sC;

    const int bm = blockIdx.y * 128;
    const int bn = blockIdx.x * 128;
    const int tid = threadIdx.x;
    const int wid = tid >> 5;
    const int lane = tid & 31;
    const int wm = (wid >> 1) * 32;   // warp M offset (4 warps)
    const int wn = (wid & 1) * 64;    // warp N offset (2 warps)

    const uint32_t sbase = (smem_u32(dsm) + 1023u) & ~1023u;

    // ldmatrix addressing. Logical layout: 128 rows x 128 bytes,
    // sw = off ^ ((off>>3)&0x70) == rowpart + (colbyte ^ ((row%8)<<4)).
    // rowpart steps of 2048 (16 rows) preserve row%8, so only colbyte needs
    // the XOR — computed per access from the FULL logical column byte.
    const int msel = lane >> 3;        // which 8x8 matrix
    const int mrow = lane & 7;
    const uint32_t xorm = (uint32_t)(mrow << 4);
    const uint32_t cb0  = (uint32_t)((msel >> 1) * 16);
    const uint32_t aRowB = (uint32_t)((wm + (msel & 1) * 8 + mrow) * 128);
    const uint32_t bRowB = (uint32_t)((wn + (msel & 1) * 8 + mrow) * 128);

    const uint32_t aH = sbase + OFF_AH + aRowB;
    const uint32_t aL = sbase + OFF_AL + aRowB;
    const uint32_t bH = sbase + OFF_BH + bRowB;
    const uint32_t bL = sbase + OFF_BL + bRowB;

    float acc[2][8][4];
#pragma unroll
    for (int b = 0; b < 2; b++)
#pragma unroll
        for (int j = 0; j < 8; j++)
#pragma unroll
            for (int x = 0; x < 4; x++) acc[b][j][x] = 0.0f;

    float4 aReg[8], bReg[8];

    const int nt = K / 64;

    // prologue load (tile 0)
#pragma unroll
    for (int i = 0; i < 8; i++) {
        const int idx = tid + i * 256;
        const int row = idx >> 4;
        const int c4  = (idx & 15) << 2;
        aReg[i] = *reinterpret_cast<const float4*>(&A[(size_t)(bm + row) * K + c4]);
        bReg[i] = *reinterpret_cast<const float4*>(&B[(size_t)(bn + row) * K + c4]);
    }

    for (int t = 0; t < nt; ++t) {
        // store current tile (convert + split + swizzle)
#pragma unroll
        for (int i = 0; i < 8; i++) {
            const int idx = tid + i * 256;
            const int row = idx >> 4;
            const int c4  = (idx & 15) << 2;
            uint32_t off = (uint32_t)(row * 128 + c4 * 2);
            uint32_t sw = off ^ ((off >> 3) & 0x70u);
            split_store(aReg[i], sbase + OFF_AH + sw, sbase + OFF_AL + sw);
            split_store(bReg[i], sbase + OFF_BH + sw, sbase + OFF_BL + sw);
        }
        __syncthreads();

        // prefetch next tile into regs (overlaps compute below)
        if (t + 1 < nt) {
            const int k0 = (t + 1) * 64;
#pragma unroll
            for (int i = 0; i < 8; i++) {
                const int idx = tid + i * 256;
                const int row = idx >> 4;
                const int c4  = (idx & 15) << 2;
                aReg[i] = *reinterpret_cast<const float4*>(&A[(size_t)(bm + row) * K + k0 + c4]);
                bReg[i] = *reinterpret_cast<const float4*>(&B[(size_t)(bn + row) * K + k0 + c4]);
            }
        }

        // compute: 4 k-steps of 16 bf16
#pragma unroll
        for (int ks = 0; ks < 4; ks++) {
            const uint32_t co = (cb0 + (uint32_t)(ks * 32)) ^ xorm;  // swizzled col byte
            uint32_t ah[2][4], al[2][4], bq[4][4];

            ldsm4(aH + co,        ah[0]);
            ldsm4(aH + 2048 + co, ah[1]);
#pragma unroll
            for (int g = 0; g < 4; g++) ldsm4(bH + g * 2048 + co, bq[g]);

            // Ah * Bh
#pragma unroll
            for (int b = 0; b < 2; b++)
#pragma unroll
                for (int g = 0; g < 4; g++) {
                    mma_bf16(acc[b][2 * g],     ah[b], bq[g][0], bq[g][2]);
                    mma_bf16(acc[b][2 * g + 1], ah[b], bq[g][1], bq[g][3]);
                }

            ldsm4(aL + co,        al[0]);
            ldsm4(aL + 2048 + co, al[1]);
            // Al * Bh
#pragma unroll
            for (int b = 0; b < 2; b++)
#pragma unroll
                for (int g = 0; g < 4; g++) {
                    mma_bf16(acc[b][2 * g],     al[b], bq[g][0], bq[g][2]);
                    mma_bf16(acc[b][2 * g + 1], al[b], bq[g][1], bq[g][3]);
                }

#pragma unroll
            for (int g = 0; g < 4; g++) ldsm4(bL + g * 2048 + co, bq[g]);
            // Ah * Bl
#pragma unroll
            for (int b = 0; b < 2; b++)
#pragma unroll
                for (int g = 0; g < 4; g++) {
                    mma_bf16(acc[b][2 * g],     ah[b], bq[g][0], bq[g][2]);
                    mma_bf16(acc[b][2 * g + 1], ah[b], bq[g][1], bq[g][3]);
                }
        }
        __syncthreads();
    }

    // epilogue: thread holds (row = lane/4, col = 2*(lane%4)) pattern per mma
    const int r0 = lane >> 2;
    const int c0 = (lane & 3) * 2;
#pragma unroll
    for (int b = 0; b < 2; b++) {
        const int mrow0 = bm + wm + b * 16 + r0;
#pragma unroll
        for (int j = 0; j < 8; j++) {
            const int col = bn + wn + j * 8 + c0;
            float bx = 0.0f, by = 0.0f;
            if (bias != nullptr) { bx = bias[col]; by = bias[col + 1]; }
            float2 v0, v1;
            v0.x = acc[b][j][0] * scale + bx;
            v0.y = acc[b][j][1] * scale + by;
            v1.x = acc[b][j][2] * scale + bx;
            v1.y = acc[b][j][3] * scale + by;
            *reinterpret_cast<float2*>(&C[(size_t)mrow0 * N + col]) = v0;
            *reinterpret_cast<float2*>(&C[(size_t)(mrow0 + 8) * N + col]) = v1;
        }
    }
}

// ---------------------------------------------------------------------------
// Transpose: src [R,C] -> dst [C,R], batched via blockIdx.z
// ---------------------------------------------------------------------------
__global__ __launch_bounds__(256)
void transpose_kernel(const float* __restrict__ src, float* __restrict__ dst,
                      int R, int C, size_t ss, size_t sd)
{
    __shared__ float tile[32][33];
    src += (size_t)blockIdx.z * ss;
    dst += (size_t)blockIdx.z * sd;
    const int c0 = blockIdx.x * 32;
    const int r0 = blockIdx.y * 32;
    const int x = threadIdx.x;
#pragma unroll
    for (int i = threadIdx.y; i < 32; i += 8)
        tile[i][x] = src[(size_t)(r0 + i) * C + c0 + x];
    __syncthreads();
#pragma unroll
    for (int i = threadIdx.y; i < 32; i += 8)
        dst[(size_t)(c0 + i) * R + r0 + x] = tile[x][i];
}

// ---------------------------------------------------------------------------
// Row softmax, in place. One block (256 threads) per row of length n.
// ---------------------------------------------------------------------------
__global__ __launch_bounds__(256)
void softmax_kernel(float* __restrict__ S, int n)
{
    float* row = S + (size_t)blockIdx.x * n;
    const int tid = threadIdx.x;
    __shared__ float sred[8];
    __shared__ float sbcast;

    float m = -3.402823466e38f;
    for (int i = tid; i < n; i += 256) m = fmaxf(m, row[i]);
#pragma unroll
    for (int o = 16; o > 0; o >>= 1)
        m = fmaxf(m, __shfl_xor_sync(0xffffffffu, m, o));
    if ((tid & 31) == 0) sred[tid >> 5] = m;
    __syncthreads();
    if (tid == 0) {
        float v = sred[0];
#pragma unroll
        for (int w = 1; w < 8; w++) v = fmaxf(v, sred[w]);
        sbcast = v;
    }
    __syncthreads();
    m = sbcast;

    float sum = 0.0f;
    for (int i = tid; i < n; i += 256) {
        float e = __expf(row[i] - m);
        row[i] = e;
        sum += e;
    }
#pragma unroll
    for (int o = 16; o > 0; o >>= 1)
        sum += __shfl_xor_sync(0xffffffffu, sum, o);
    __syncthreads();
    if ((tid & 31) == 0) sred[tid >> 5] = sum;
    __syncthreads();
    if (tid == 0) {
        float v = 0.0f;
#pragma unroll
        for (int w = 0; w < 8; w++) v += sred[w];
        sbcast = 1.0f / v;
    }
    __syncthreads();
    const float inv = sbcast;
    for (int i = tid; i < n; i += 256) row[i] *= inv;
}

// ---------------------------------------------------------------------------
// Launch
// ---------------------------------------------------------------------------
extern "C" void kernel_launch(void* const* d_in, const int* in_sizes, int n_in,
                              void* d_out, int out_size)
{
    (void)in_sizes; (void)n_in; (void)out_size;
    const float* X  = (const float*)d_in[0];
    const float* Wq = (const float*)d_in[1];
    const float* bq = (const float*)d_in[2];
    const float* Wk = (const float*)d_in[3];
    const float* bk = (const float*)d_in[4];
    const float* Wv = (const float*)d_in[5];
    const float* bv = (const float*)d_in[6];
    const float* Wh = (const float*)d_in[7];
    const float* bh = (const float*)d_in[8];
    float* out = (float*)d_out;

    float *Q, *Kp, *V, *Vt, *S, *C, *WT;
    cudaGetSymbolAddress((void**)&Q,  gQ);
    cudaGetSymbolAddress((void**)&Kp, gK);
    cudaGetSymbolAddress((void**)&V,  gV);
    cudaGetSymbolAddress((void**)&Vt, gVt);
    cudaGetSymbolAddress((void**)&S,  gS);
    cudaGetSymbolAddress((void**)&C,  gC);
    cudaGetSymbolAddress((void**)&WT, gWT);

    cudaFuncSetAttribute(gemm_mma, cudaFuncAttributeMaxDynamicSharedMemorySize, GEMM_DSM);

    const dim3 tblk(32, 8);
    const dim3 gWt(HID / 32, HID / 32, 1);
    transpose_kernel<<<gWt, tblk>>>(Wq, WT + 0 * (size_t)HID * HID, HID, HID, 0, 0);
    transpose_kernel<<<gWt, tblk>>>(Wk, WT + 1 * (size_t)HID * HID, HID, HID, 0, 0);
    transpose_kernel<<<gWt, tblk>>>(Wv, WT + 2 * (size_t)HID * HID, HID, HID, 0, 0);
    transpose_kernel<<<gWt, tblk>>>(Wh, WT + 3 * (size_t)HID * HID, HID, HID, 0, 0);

    const float scale = 0.03125f;  // 1/sqrt(1024)

    // QKV projections
    const dim3 gProj(HID / 128, MTOT / 128, 1);
    gemm_mma<<<gProj, 256, GEMM_DSM>>>(X, WT + 0 * (size_t)HID * HID, bq, Q,
                                       MTOT, HID, HID, 1.0f, 0, 0, 0);
    gemm_mma<<<gProj, 256, GEMM_DSM>>>(X, WT + 1 * (size_t)HID * HID, bk, Kp,
                                       MTOT, HID, HID, 1.0f, 0, 0, 0);
    gemm_mma<<<gProj, 256, GEMM_DSM>>>(X, WT + 2 * (size_t)HID * HID, bv, V,
                                       MTOT, HID, HID, 1.0f, 0, 0, 0);

    // V^T per batch
    const dim3 gVtT(HID / 32, SEQ / 32, BSZ);
    transpose_kernel<<<gVtT, tblk>>>(V, Vt, SEQ, HID,
                                     (size_t)SEQ * HID, (size_t)HID * SEQ);

    // scores = scale * Q @ K^T (batched)
    const dim3 gScore(SEQ / 128, SEQ / 128, BSZ);
    gemm_mma<<<gScore, 256, GEMM_DSM>>>(Q, Kp, nullptr, S,
                                        SEQ, SEQ, HID, scale,
                                        (size_t)SEQ * HID, (size_t)SEQ * HID,
                                        (size_t)SEQ * SEQ);

    softmax_kernel<<<MTOT, 256>>>(S, SEQ);

    // context = attn @ V = attn @ Vt^T (batched)
    const dim3 gCtx(HID / 128, SEQ / 128, BSZ);
    gemm_mma<<<gCtx, 256, GEMM_DSM>>>(S, Vt, nullptr, C,
                                      SEQ, HID, SEQ, 1.0f,
                                      (size_t)SEQ * SEQ, (size_t)HID * SEQ,
                                      (size_t)SEQ * HID);

    // output projection
    gemm_mma<<<gProj, 256, GEMM_DSM>>>(C, WT + 3 * (size_t)HID * HID, bh, out,
                                       MTOT, HID, HID, 1.0f, 0, 0, 0);
}

// round 15
// speedup vs baseline: 2.6730x; 1.1907x over previous
#include <cuda_runtime.h>
#include <cuda_bf16.h>
#include <cstdint>
#include <math.h>

// ---------------------------------------------------------------------------
// SimpleAttention, mma.sync bf16 3-term split.
// R13: operands preconverted to split-bf16 (hi,lo) arrays ONCE; GEMM inner
// loop is pure cp.async -> ldmatrix -> mma with double-buffered smem.
// ---------------------------------------------------------------------------

#define SEQ  2048
#define HID  1024
#define BSZ  4
#define MTOT (SEQ * BSZ)   // 8192

__device__ __nv_bfloat16 gXh[(size_t)MTOT * HID], gXl[(size_t)MTOT * HID];
__device__ __nv_bfloat16 gWTh[(size_t)4 * HID * HID], gWTl[(size_t)4 * HID * HID];
__device__ __nv_bfloat16 gQh[(size_t)MTOT * HID], gQl[(size_t)MTOT * HID];
__device__ __nv_bfloat16 gKh[(size_t)MTOT * HID], gKl[(size_t)MTOT * HID];
__device__ float         gV [(size_t)MTOT * HID];
__device__ __nv_bfloat16 gVth[(size_t)MTOT * HID], gVtl[(size_t)MTOT * HID];
__device__ float         gS [(size_t)BSZ * SEQ * SEQ];
__device__ __nv_bfloat16 gSh[(size_t)BSZ * SEQ * SEQ], gSl[(size_t)BSZ * SEQ * SEQ];
__device__ __nv_bfloat16 gCh[(size_t)MTOT * HID], gCl[(size_t)MTOT * HID];

// smem: two 64KB buffers, each: Ah | Al | Bh | Bl (128 rows x 64 bf16, 128B rows)
#define OFF_AH 0
#define OFF_AL 16384
#define OFF_BH 32768
#define OFF_BL 49152
#define BUFB   65536
#define GEMM_DSM (2 * BUFB + 1024)

__device__ __forceinline__ uint32_t smem_u32(const void* p) {
    uint32_t a;
    asm("{ .reg .u64 t; cvta.to.shared.u64 t, %1; cvt.u32.u64 %0, t; }"
        : "=r"(a) : "l"(p));
    return a;
}

__device__ __forceinline__ void cp16(uint32_t dst, const void* src) {
    asm volatile("cp.async.cg.shared.global [%0], [%1], 16;"
                 :: "r"(dst), "l"(src) : "memory");
}

__device__ __forceinline__ void ldsm4(uint32_t addr, uint32_t* r) {
    asm volatile("ldmatrix.sync.aligned.m8n8.x4.shared.b16 {%0,%1,%2,%3}, [%4];"
                 : "=r"(r[0]), "=r"(r[1]), "=r"(r[2]), "=r"(r[3]) : "r"(addr));
}

__device__ __forceinline__ void mma_bf16(float* d, const uint32_t* a,
                                         uint32_t b0, uint32_t b1) {
    asm volatile("mma.sync.aligned.m16n8k16.row.col.f32.bf16.bf16.f32 "
                 "{%0,%1,%2,%3}, {%4,%5,%6,%7}, {%8,%9}, {%0,%1,%2,%3};"
                 : "+f"(d[0]), "+f"(d[1]), "+f"(d[2]), "+f"(d[3])
                 : "r"(a[0]), "r"(a[1]), "r"(a[2]), "r"(a[3]), "r"(b0), "r"(b1));
}

// ---------------------------------------------------------------------------
// GEMM: out = scale * (A[M,K] @ B[N,K]^T) (+ bias[N])
// A,B given as split-bf16 (hi,lo) K-major arrays. Batched via blockIdx.z.
// OMODE 0: write fp32 outF.   OMODE 1: write split bf16 outH/outL.
// M%128==0, N%128==0, K%64==0.
// ---------------------------------------------------------------------------
template <int OMODE>
__global__ __launch_bounds__(256, 1)
void gemm_async(const __nv_bfloat16* __restrict__ Ah, const __nv_bfloat16* __restrict__ Al,
                const __nv_bfloat16* __restrict__ Bh, const __nv_bfloat16* __restrict__ Bl,
                const float* __restrict__ bias,
                float* __restrict__ outF,
                __nv_bfloat16* __restrict__ outH, __nv_bfloat16* __restrict__ outL,
                int M, int N, int K, float scale,
                size_t sA, size_t sB, size_t sC)
{
    extern __shared__ char dsm[];
    Ah += (size_t)blockIdx.z * sA;  Al += (size_t)blockIdx.z * sA;
    Bh += (size_t)blockIdx.z * sB;  Bl += (size_t)blockIdx.z * sB;

    const int bm = blockIdx.y * 128;
    const int bn = blockIdx.x * 128;
    const int tid = threadIdx.x;
    const int wid = tid >> 5;
    const int lane = tid & 31;
    const int wm = (wid >> 1) * 32;
    const int wn = (wid & 1) * 64;

    const uint32_t sbase = (smem_u32(dsm) + 1023u) & ~1023u;

    // loader mapping: 1024 16B-chunks per array; 4 per thread
    const int ldr = tid >> 3;   // 0..31, +i*32
    const int ldc = tid & 7;    // 16B chunk within row

    // ldmatrix addressing (verified swizzle: sw = rowpart + (colbyte ^ ((row%8)<<4)))
    const int msel = lane >> 3;
    const int mrow = lane & 7;
    const uint32_t xorm = (uint32_t)(mrow << 4);
    const uint32_t cb0  = (uint32_t)((msel >> 1) * 16);
    const uint32_t aRowB = (uint32_t)((wm + (msel & 1) * 8 + mrow) * 128);
    const uint32_t bRowB = (uint32_t)((wn + (msel & 1) * 8 + mrow) * 128);

    float acc[2][8][4];
#pragma unroll
    for (int b = 0; b < 2; b++)
#pragma unroll
        for (int j = 0; j < 8; j++)
#pragma unroll
            for (int x = 0; x < 4; x++) acc[b][j][x] = 0.0f;

    const int nt = K / 64;

    // ---- async load issue for tile t into buffer bb ----
    auto issue = [&](int t, uint32_t bb) {
        const int k0 = t * 64;
#pragma unroll
        for (int i = 0; i < 4; i++) {
            const int row = ldr + i * 32;
            uint32_t off = (uint32_t)(row * 128 + ldc * 16);
            uint32_t sw  = off ^ ((off >> 3) & 0x70u);
            const size_t ga = (size_t)(bm + row) * K + k0 + ldc * 8;
            const size_t gb = (size_t)(bn + row) * K + k0 + ldc * 8;
            cp16(bb + OFF_AH + sw, Ah + ga);
            cp16(bb + OFF_AL + sw, Al + ga);
            cp16(bb + OFF_BH + sw, Bh + gb);
            cp16(bb + OFF_BL + sw, Bl + gb);
        }
        asm volatile("cp.async.commit_group;" ::: "memory");
    };

    issue(0, sbase);

    for (int t = 0; t < nt; ++t) {
        const uint32_t bb = sbase + (uint32_t)(t & 1) * BUFB;
        if (t + 1 < nt) {
            issue(t + 1, sbase + (uint32_t)((t + 1) & 1) * BUFB);
            asm volatile("cp.async.wait_group 1;" ::: "memory");
        } else {
            asm volatile("cp.async.wait_group 0;" ::: "memory");
        }
        __syncthreads();

        const uint32_t aH = bb + OFF_AH + aRowB;
        const uint32_t aL = bb + OFF_AL + aRowB;
        const uint32_t bH = bb + OFF_BH + bRowB;
        const uint32_t bL = bb + OFF_BL + bRowB;

#pragma unroll
        for (int ks = 0; ks < 4; ks++) {
            const uint32_t co = (cb0 + (uint32_t)(ks * 32)) ^ xorm;
            uint32_t ah[2][4], al[2][4], bq[4][4];

            ldsm4(aH + co,        ah[0]);
            ldsm4(aH + 2048 + co, ah[1]);
#pragma unroll
            for (int g = 0; g < 4; g++) ldsm4(bH + g * 2048 + co, bq[g]);

            // Ah * Bh
#pragma unroll
            for (int b = 0; b < 2; b++)
#pragma unroll
                for (int g = 0; g < 4; g++) {
                    mma_bf16(acc[b][2 * g],     ah[b], bq[g][0], bq[g][2]);
                    mma_bf16(acc[b][2 * g + 1], ah[b], bq[g][1], bq[g][3]);
                }

            ldsm4(aL + co,        al[0]);
            ldsm4(aL + 2048 + co, al[1]);
            // Al * Bh
#pragma unroll
            for (int b = 0; b < 2; b++)
#pragma unroll
                for (int g = 0; g < 4; g++) {
                    mma_bf16(acc[b][2 * g],     al[b], bq[g][0], bq[g][2]);
                    mma_bf16(acc[b][2 * g + 1], al[b], bq[g][1], bq[g][3]);
                }

#pragma unroll
            for (int g = 0; g < 4; g++) ldsm4(bL + g * 2048 + co, bq[g]);
            // Ah * Bl
#pragma unroll
            for (int b = 0; b < 2; b++)
#pragma unroll
                for (int g = 0; g < 4; g++) {
                    mma_bf16(acc[b][2 * g],     ah[b], bq[g][0], bq[g][2]);
                    mma_bf16(acc[b][2 * g + 1], ah[b], bq[g][1], bq[g][3]);
                }
        }
        __syncthreads();
    }

    // epilogue
    const int r0 = lane >> 2;
    const int c0 = (lane & 3) * 2;
#pragma unroll
    for (int b = 0; b < 2; b++) {
        const int mrow0 = bm + wm + b * 16 + r0;
#pragma unroll
        for (int j = 0; j < 8; j++) {
            const int col = bn + wn + j * 8 + c0;
            float bx = 0.0f, by = 0.0f;
            if (bias != nullptr) { bx = bias[col]; by = bias[col + 1]; }
            float v00 = acc[b][j][0] * scale + bx;
            float v01 = acc[b][j][1] * scale + by;
            float v10 = acc[b][j][2] * scale + bx;
            float v11 = acc[b][j][3] * scale + by;
            if (OMODE == 0) {
                float* C = outF + (size_t)blockIdx.z * sC;
                *reinterpret_cast<float2*>(&C[(size_t)mrow0 * N + col]) = make_float2(v00, v01);
                *reinterpret_cast<float2*>(&C[(size_t)(mrow0 + 8) * N + col]) = make_float2(v10, v11);
            } else {
                __nv_bfloat16* H = outH + (size_t)blockIdx.z * sC;
                __nv_bfloat16* L = outL + (size_t)blockIdx.z * sC;
                __nv_bfloat16 h00 = __float2bfloat16_rn(v00), h01 = __float2bfloat16_rn(v01);
                __nv_bfloat16 h10 = __float2bfloat16_rn(v10), h11 = __float2bfloat16_rn(v11);
                __nv_bfloat162 hp0 = __nv_bfloat162(h00, h01);
                __nv_bfloat162 hp1 = __nv_bfloat162(h10, h11);
                __nv_bfloat162 lp0 = __floats2bfloat162_rn(v00 - __bfloat162float(h00),
                                                           v01 - __bfloat162float(h01));
                __nv_bfloat162 lp1 = __floats2bfloat162_rn(v10 - __bfloat162float(h10),
                                                           v11 - __bfloat162float(h11));
                *reinterpret_cast<uint32_t*>(&H[(size_t)mrow0 * N + col]) =
                    *reinterpret_cast<uint32_t*>(&hp0);
                *reinterpret_cast<uint32_t*>(&H[(size_t)(mrow0 + 8) * N + col]) =
                    *reinterpret_cast<uint32_t*>(&hp1);
                *reinterpret_cast<uint32_t*>(&L[(size_t)mrow0 * N + col]) =
                    *reinterpret_cast<uint32_t*>(&lp0);
                *reinterpret_cast<uint32_t*>(&L[(size_t)(mrow0 + 8) * N + col]) =
                    *reinterpret_cast<uint32_t*>(&lp1);
            }
        }
    }
}

// ---------------------------------------------------------------------------
// Elementwise fp32 -> split bf16 (hi,lo). n4 = count of float4 groups.
// ---------------------------------------------------------------------------
__global__ __launch_bounds__(256)
void convert_split(const float* __restrict__ src, __nv_bfloat16* __restrict__ dh,
                   __nv_bfloat16* __restrict__ dl, int n4)
{
    int i = blockIdx.x * blockDim.x + threadIdx.x;
    if (i >= n4) return;
    float4 v = reinterpret_cast<const float4*>(src)[i];
    __nv_bfloat16 h0 = __float2bfloat16_rn(v.x), h1 = __float2bfloat16_rn(v.y);
    __nv_bfloat16 h2 = __float2bfloat16_rn(v.z), h3 = __float2bfloat16_rn(v.w);
    __nv_bfloat162 hp0 = __nv_bfloat162(h0, h1), hp1 = __nv_bfloat162(h2, h3);
    __nv_bfloat162 lp0 = __floats2bfloat162_rn(v.x - __bfloat162float(h0),
                                               v.y - __bfloat162float(h1));
    __nv_bfloat162 lp1 = __floats2bfloat162_rn(v.z - __bfloat162float(h2),
                                               v.w - __bfloat162float(h3));
    uint2 hh, ll;
    hh.x = *reinterpret_cast<uint32_t*>(&hp0); hh.y = *reinterpret_cast<uint32_t*>(&hp1);
    ll.x = *reinterpret_cast<uint32_t*>(&lp0); ll.y = *reinterpret_cast<uint32_t*>(&lp1);
    reinterpret_cast<uint2*>(dh)[i] = hh;
    reinterpret_cast<uint2*>(dl)[i] = ll;
}

// ---------------------------------------------------------------------------
// Transpose fp32 [R,C] -> split bf16 [C,R]. Batched via blockIdx.z.
// ---------------------------------------------------------------------------
__global__ __launch_bounds__(256)
void transpose_split(const float* __restrict__ src, __nv_bfloat16* __restrict__ dh,
                     __nv_bfloat16* __restrict__ dl, int R, int C, size_t ss, size_t sd)
{
    __shared__ float tile[32][33];
    src += (size_t)blockIdx.z * ss;
    dh  += (size_t)blockIdx.z * sd;
    dl  += (size_t)blockIdx.z * sd;
    const int c0 = blockIdx.x * 32;
    const int r0 = blockIdx.y * 32;
    const int x = threadIdx.x;
#pragma unroll
    for (int i = threadIdx.y; i < 32; i += 8)
        tile[i][x] = src[(size_t)(r0 + i) * C + c0 + x];
    __syncthreads();
#pragma unroll
    for (int i = threadIdx.y; i < 32; i += 8) {
        float v = tile[x][i];
        __nv_bfloat16 h = __float2bfloat16_rn(v);
        dh[(size_t)(c0 + i) * R + r0 + x] = h;
        dl[(size_t)(c0 + i) * R + r0 + x] = __float2bfloat16_rn(v - __bfloat162float(h));
    }
}

// ---------------------------------------------------------------------------
// Softmax: fp32 scores row -> split bf16 probs. One block per row.
// ---------------------------------------------------------------------------
__global__ __launch_bounds__(256)
void softmax_split(const float* __restrict__ S, __nv_bfloat16* __restrict__ Sh,
                   __nv_bfloat16* __restrict__ Sl, int n)
{
    const float* row = S + (size_t)blockIdx.x * n;
    __nv_bfloat16* rh = Sh + (size_t)blockIdx.x * n;
    __nv_bfloat16* rl = Sl + (size_t)blockIdx.x * n;
    const int tid = threadIdx.x;
    __shared__ float sred[8];
    __shared__ float sm, sinv;

    float m = -3.402823466e38f;
    for (int i = tid; i < n; i += 256) m = fmaxf(m, row[i]);
#pragma unroll
    for (int o = 16; o > 0; o >>= 1)
        m = fmaxf(m, __shfl_xor_sync(0xffffffffu, m, o));
    if ((tid & 31) == 0) sred[tid >> 5] = m;
    __syncthreads();
    if (tid == 0) {
        float v = sred[0];
#pragma unroll
        for (int w = 1; w < 8; w++) v = fmaxf(v, sred[w]);
        sm = v;
    }
    __syncthreads();
    m = sm;

    float sum = 0.0f;
    for (int i = tid; i < n; i += 256) sum += __expf(row[i] - m);
#pragma unroll
    for (int o = 16; o > 0; o >>= 1)
        sum += __shfl_xor_sync(0xffffffffu, sum, o);
    __syncthreads();
    if ((tid & 31) == 0) sred[tid >> 5] = sum;
    __syncthreads();
    if (tid == 0) {
        float v = 0.0f;
#pragma unroll
        for (int w = 0; w < 8; w++) v += sred[w];
        sinv = 1.0f / v;
    }
    __syncthreads();
    const float inv = sinv;

    // write pairs (n even)
    for (int i = tid * 2; i < n; i += 512) {
        float p0 = __expf(row[i] - m) * inv;
        float p1 = __expf(row[i + 1] - m) * inv;
        __nv_bfloat16 h0 = __float2bfloat16_rn(p0), h1 = __float2bfloat16_rn(p1);
        __nv_bfloat162 hp = __nv_bfloat162(h0, h1);
        __nv_bfloat162 lp = __floats2bfloat162_rn(p0 - __bfloat162float(h0),
                                                  p1 - __bfloat162float(h1));
        *reinterpret_cast<uint32_t*>(&rh[i]) = *reinterpret_cast<uint32_t*>(&hp);
        *reinterpret_cast<uint32_t*>(&rl[i]) = *reinterpret_cast<uint32_t*>(&lp);
    }
}

// ---------------------------------------------------------------------------
// Launch
// ---------------------------------------------------------------------------
extern "C" void kernel_launch(void* const* d_in, const int* in_sizes, int n_in,
                              void* d_out, int out_size)
{
    (void)in_sizes; (void)n_in; (void)out_size;
    const float* X  = (const float*)d_in[0];
    const float* Wq = (const float*)d_in[1];
    const float* bq = (const float*)d_in[2];
    const float* Wk = (const float*)d_in[3];
    const float* bk = (const float*)d_in[4];
    const float* Wv = (const float*)d_in[5];
    const float* bv = (const float*)d_in[6];
    const float* Wh = (const float*)d_in[7];
    const float* bh = (const float*)d_in[8];
    float* out = (float*)d_out;

    __nv_bfloat16 *Xh, *Xl, *WTh, *WTl, *Qh, *Ql, *Kh, *Kl, *Vth, *Vtl, *Sh, *Sl, *Ch, *Cl;
    float *V, *S;
    cudaGetSymbolAddress((void**)&Xh,  gXh);  cudaGetSymbolAddress((void**)&Xl,  gXl);
    cudaGetSymbolAddress((void**)&WTh, gWTh); cudaGetSymbolAddress((void**)&WTl, gWTl);
    cudaGetSymbolAddress((void**)&Qh,  gQh);  cudaGetSymbolAddress((void**)&Ql,  gQl);
    cudaGetSymbolAddress((void**)&Kh,  gKh);  cudaGetSymbolAddress((void**)&Kl,  gKl);
    cudaGetSymbolAddress((void**)&V,   gV);
    cudaGetSymbolAddress((void**)&Vth, gVth); cudaGetSymbolAddress((void**)&Vtl, gVtl);
    cudaGetSymbolAddress((void**)&S,   gS);
    cudaGetSymbolAddress((void**)&Sh,  gSh);  cudaGetSymbolAddress((void**)&Sl,  gSl);
    cudaGetSymbolAddress((void**)&Ch,  gCh);  cudaGetSymbolAddress((void**)&Cl,  gCl);

    cudaFuncSetAttribute(gemm_async<0>, cudaFuncAttributeMaxDynamicSharedMemorySize, GEMM_DSM);
    cudaFuncSetAttribute(gemm_async<1>, cudaFuncAttributeMaxDynamicSharedMemorySize, GEMM_DSM);

    const float scale = 0.03125f;  // 1/sqrt(1024)
    const size_t WW = (size_t)HID * HID;

    // X -> split
    convert_split<<<(MTOT * HID / 4 + 255) / 256, 256>>>(X, Xh, Xl, MTOT * HID / 4);

    // weights -> transposed split
    const dim3 tblk(32, 8);
    const dim3 gWt(HID / 32, HID / 32, 1);
    transpose_split<<<gWt, tblk>>>(Wq, WTh + 0 * WW, WTl + 0 * WW, HID, HID, 0, 0);
    transpose_split<<<gWt, tblk>>>(Wk, WTh + 1 * WW, WTl + 1 * WW, HID, HID, 0, 0);
    transpose_split<<<gWt, tblk>>>(Wv, WTh + 2 * WW, WTl + 2 * WW, HID, HID, 0, 0);
    transpose_split<<<gWt, tblk>>>(Wh, WTh + 3 * WW, WTl + 3 * WW, HID, HID, 0, 0);

    // QKV projections
    const dim3 gProj(HID / 128, MTOT / 128, 1);
    gemm_async<1><<<gProj, 256, GEMM_DSM>>>(Xh, Xl, WTh + 0 * WW, WTl + 0 * WW, bq,
                                            nullptr, Qh, Ql, MTOT, HID, HID, 1.0f, 0, 0, 0);
    gemm_async<1><<<gProj, 256, GEMM_DSM>>>(Xh, Xl, WTh + 1 * WW, WTl + 1 * WW, bk,
                                            nullptr, Kh, Kl, MTOT, HID, HID, 1.0f, 0, 0, 0);
    gemm_async<0><<<gProj, 256, GEMM_DSM>>>(Xh, Xl, WTh + 2 * WW, WTl + 2 * WW, bv,
                                            V, nullptr, nullptr, MTOT, HID, HID, 1.0f, 0, 0, 0);

    // V -> Vt split (per batch)
    const dim3 gVtT(HID / 32, SEQ / 32, BSZ);
    transpose_split<<<gVtT, tblk>>>(V, Vth, Vtl, SEQ, HID,
                                    (size_t)SEQ * HID, (size_t)HID * SEQ);

    // scores = scale * Q @ K^T
    const dim3 gScore(SEQ / 128, SEQ / 128, BSZ);
    gemm_async<0><<<gScore, 256, GEMM_DSM>>>(Qh, Ql, Kh, Kl, nullptr,
                                             S, nullptr, nullptr, SEQ, SEQ, HID, scale,
                                             (size_t)SEQ * HID, (size_t)SEQ * HID,
                                             (size_t)SEQ * SEQ);

    // softmax -> split probs
    softmax_split<<<MTOT, 256>>>(S, Sh, Sl, SEQ);

    // context = probs @ Vt^T
    const dim3 gCtx(HID / 128, SEQ / 128, BSZ);
    gemm_async<1><<<gCtx, 256, GEMM_DSM>>>(Sh, Sl, Vth, Vtl, nullptr,
                                           nullptr, Ch, Cl, SEQ, HID, SEQ, 1.0f,
                                           (size_t)SEQ * SEQ, (size_t)HID * SEQ,
                                           (size_t)SEQ * HID);

    // output projection
    gemm_async<0><<<gProj, 256, GEMM_DSM>>>(Ch, Cl, WTh + 3 * WW, WTl + 3 * WW, bh,
                                            out, nullptr, nullptr, MTOT, HID, HID, 1.0f, 0, 0, 0);
}